// round 1
// baseline (speedup 1.0000x reference)
#include <cuda_runtime.h>
#include <cuda_bf16.h>

// F0 extraction via raw autocorrelation argmax.
// argmax_p sum_t xn[t]*xn[t+p] == argmax_p sum_t x[t]*x[t+p]  (normalization is
// a positive per-frame scalar), so the norm/divide is skipped entirely.

#define SR_I        16000
#define HOP         256
#define FRAME_LEN   512
#define MIN_PERIOD  32
#define N_LAGS      224      // lags 32..255 = 7 * 32
#define LAGS_PER_LANE 7
#define FRAMES_PER_BLOCK 8
#define T_LEN       163840
#define N_FRAMES    641
#define BUF         768      // 512 data + zero pad (max read idx = 479+249+7 = 735)

__global__ __launch_bounds__(256) void f0_autocorr_kernel(
    const float* __restrict__ x,   // (64, 1, 163840)
    float* __restrict__ out)       // (64, 641)
{
    __shared__ float sbuf[FRAMES_PER_BLOCK][BUF];

    const int b      = blockIdx.y;
    const int f_base = blockIdx.x * FRAMES_PER_BLOCK;
    const float* __restrict__ xb = x + (size_t)b * T_LEN;
    const int tid = threadIdx.x;

    // Cooperative fill: each frame row w holds xpad[f*HOP .. f*HOP+512) then zeros.
    // xpad[j] = x[reflect(j - 256)]  (numpy 'reflect', pad = FRAME_LEN/2 = 256).
    for (int i = tid; i < FRAMES_PER_BLOCK * BUF; i += 256) {
        const int w = i / BUF;
        const int j = i - w * BUF;
        float v = 0.0f;
        if (j < FRAME_LEN) {
            int g = (f_base + w) * HOP + j - (FRAME_LEN / 2);
            if (g < 0) g = -g;
            if (g >= T_LEN) g = 2 * (T_LEN - 1) - g;
            v = xb[g];
        }
        sbuf[w][j] = v;
    }
    __syncthreads();

    const int w    = tid >> 5;
    const int lane = tid & 31;
    const int f    = f_base + w;
    const float* __restrict__ s = sbuf[w];

    // Lane owns 7 consecutive lags: p = base .. base+6, base = 32 + 7*lane.
    const int base = MIN_PERIOD + LAGS_PER_LANE * lane;   // max 249

    float acc[LAGS_PER_LANE];
    float win[LAGS_PER_LANE];   // rolling window: win[k] = s[t + base + k]
#pragma unroll
    for (int k = 0; k < LAGS_PER_LANE; ++k) {
        acc[k] = 0.0f;
        win[k] = s[base + k];
    }

    // t-loop: 480 steps. Lanes whose lag range ends earlier read zeros from the
    // padded tail of sbuf -> contributions vanish, no predication needed.
    // Broadcast load s[t] (conflict-free), feed load stride-7 (7 coprime 32 ->
    // all distinct banks, conflict-free). Unroll by 7 so the window rotation
    // becomes pure register renaming (no MOV chain).
#pragma unroll 7
    for (int t = 0; t < FRAME_LEN - MIN_PERIOD; ++t) {   // 480
        const float sb = s[t];
#pragma unroll
        for (int k = 0; k < LAGS_PER_LANE; ++k)
            acc[k] = fmaf(sb, win[k], acc[k]);
#pragma unroll
        for (int k = 0; k < LAGS_PER_LANE - 1; ++k)
            win[k] = win[k + 1];
        win[LAGS_PER_LANE - 1] = s[t + base + LAGS_PER_LANE];
    }

    // Per-lane argmax, first-index (lowest lag) wins ties.
    float bv = acc[0];
    int   bp = base;
#pragma unroll
    for (int k = 1; k < LAGS_PER_LANE; ++k) {
        if (acc[k] > bv) { bv = acc[k]; bp = base + k; }
    }

    // Warp argmax with lowest-lag tie break (associative + commutative combine).
#pragma unroll
    for (int off = 16; off > 0; off >>= 1) {
        const float ov = __shfl_xor_sync(0xffffffffu, bv, off);
        const int   op = __shfl_xor_sync(0xffffffffu, bp, off);
        if (ov > bv || (ov == bv && op < bp)) { bv = ov; bp = op; }
    }

    if (lane == 0 && f < N_FRAMES) {
        float f0 = (float)SR_I / ((float)bp + 1e-8f);
        f0 = fminf(fmaxf(f0, 50.0f), 500.0f);
        out[(size_t)b * N_FRAMES + f] = f0;
    }
}

extern "C" void kernel_launch(void* const* d_in, const int* in_sizes, int n_in,
                              void* d_out, int out_size)
{
    const float* x = (const float*)d_in[0];
    float* out = (float*)d_out;
    dim3 grid((N_FRAMES + FRAMES_PER_BLOCK - 1) / FRAMES_PER_BLOCK, 64);
    f0_autocorr_kernel<<<grid, 256>>>(x, out);
}

// round 4
// speedup vs baseline: 1.0849x; 1.0849x over previous
#include <cuda_runtime.h>
#include <cuda_bf16.h>

// F0 via raw autocorrelation argmax (normalization is a positive per-frame
// scalar -> argmax invariant -> skipped).
// R2: two frames packed into f32x2 lanes; all inner-loop math is fma.rn.f32x2
// (FFMA2), halving issue slots per MAC. Frames stored interleaved in smem so
// every operand is a naturally aligned 64-bit pair.

#define SR_I        16000
#define HOP         256
#define FRAME_LEN   512
#define MIN_PERIOD  32
#define MAX_LAG_INC 255        // lags 32..255
#define LAGS_PER_LANE 7
#define PAIRS_PER_BLOCK 8      // 8 warps, each warp = 2 frames
#define T_LEN       163840
#define N_FRAMES    641
#define BUF         736        // float2 slots: 512 data + zero pad (max idx 735)

#define FMA_F32X2(d, a, b, c) \
    asm("fma.rn.f32x2 %0, %1, %2, %3;" : "=l"(d) : "l"(a), "l"(b), "l"(c))

__device__ __forceinline__ unsigned long long pack2(float2 v) {
    unsigned long long r;
    asm("mov.b64 %0, {%1, %2};" : "=l"(r) : "f"(v.x), "f"(v.y));
    return r;
}
__device__ __forceinline__ float2 unpack2(unsigned long long v) {
    float2 r;
    asm("mov.b64 {%0, %1}, %2;" : "=f"(r.x), "=f"(r.y) : "l"(v));
    return r;
}

__global__ __launch_bounds__(256) void f0_autocorr2_kernel(
    const float* __restrict__ x,   // (64, 1, 163840)
    float* __restrict__ out)       // (64, 641)
{
    __shared__ float2 sbuf[PAIRS_PER_BLOCK][BUF];

    const int b      = blockIdx.y;
    const int f_base = blockIdx.x * (2 * PAIRS_PER_BLOCK);   // first frame of block
    const float* __restrict__ xb = x + (size_t)b * T_LEN;
    const int tid = threadIdx.x;

    // Fill: pair p holds frames (f_base+2p, f_base+2p+1) interleaved.
    // xpad[j] = x[reflect(j - 256)]  (numpy 'reflect', pad = 256).
    for (int i = tid; i < PAIRS_PER_BLOCK * BUF; i += 256) {
        const int p = i / BUF;
        const int j = i - p * BUF;
        float2 v = make_float2(0.0f, 0.0f);
        if (j < FRAME_LEN) {
            const int f0 = f_base + 2 * p;
            int g0 = f0 * HOP + j - (FRAME_LEN / 2);
            int g1 = g0 + HOP;
            if (g0 < 0) g0 = -g0;
            if (g0 >= T_LEN) g0 = 2 * (T_LEN - 1) - g0;
            if (g1 >= T_LEN) g1 = 2 * (T_LEN - 1) - g1;   // g1 >= g0+? g1 can't be <0
            v.x = xb[g0];
            v.y = xb[g1];
        }
        sbuf[p][j] = v;
    }
    __syncthreads();

    const int w    = tid >> 5;           // warp = pair index
    const int lane = tid & 31;
    const float2* __restrict__ s2 = sbuf[w];

    const int base = MIN_PERIOD + LAGS_PER_LANE * lane;   // 32..249, exactly 224 lags

    unsigned long long acc[LAGS_PER_LANE];
    unsigned long long win[LAGS_PER_LANE];
#pragma unroll
    for (int k = 0; k < LAGS_PER_LANE; ++k) {
        acc[k] = 0ull;
        win[k] = pack2(s2[base + k]);
    }

    // 480 steps; padded zeros past index 511 make short-lag tails vanish.
#pragma unroll 8
    for (int t = 0; t < FRAME_LEN - MIN_PERIOD; ++t) {
        const unsigned long long sb = pack2(s2[t]);       // LDS.64 broadcast
#pragma unroll
        for (int k = 0; k < LAGS_PER_LANE; ++k)
            FMA_F32X2(acc[k], sb, win[k], acc[k]);
#pragma unroll
        for (int k = 0; k < LAGS_PER_LANE - 1; ++k)
            win[k] = win[k + 1];
        win[LAGS_PER_LANE - 1] = pack2(s2[t + base + LAGS_PER_LANE]);  // LDS.64, conflict-free
    }

    // Per-lane argmax for each packed frame (first/lowest lag wins ties).
    float bvx, bvy; int bpx, bpy;
    {
        float2 a0 = unpack2(acc[0]);
        bvx = a0.x; bvy = a0.y; bpx = base; bpy = base;
#pragma unroll
        for (int k = 1; k < LAGS_PER_LANE; ++k) {
            float2 a = unpack2(acc[k]);
            if (a.x > bvx) { bvx = a.x; bpx = base + k; }
            if (a.y > bvy) { bvy = a.y; bpy = base + k; }
        }
    }

    // Warp argmax, lowest-lag tie break.
#pragma unroll
    for (int off = 16; off > 0; off >>= 1) {
        const float ovx = __shfl_xor_sync(0xffffffffu, bvx, off);
        const int   opx = __shfl_xor_sync(0xffffffffu, bpx, off);
        const float ovy = __shfl_xor_sync(0xffffffffu, bvy, off);
        const int   opy = __shfl_xor_sync(0xffffffffu, bpy, off);
        if (ovx > bvx || (ovx == bvx && opx < bpx)) { bvx = ovx; bpx = opx; }
        if (ovy > bvy || (ovy == bvy && opy < bpy)) { bvy = ovy; bpy = opy; }
    }

    if (lane == 0) {
        const int f0 = f_base + 2 * w;
        if (f0 < N_FRAMES) {
            float r = (float)SR_I / ((float)bpx + 1e-8f);
            out[(size_t)b * N_FRAMES + f0] = fminf(fmaxf(r, 50.0f), 500.0f);
        }
        if (f0 + 1 < N_FRAMES) {
            float r = (float)SR_I / ((float)bpy + 1e-8f);
            out[(size_t)b * N_FRAMES + f0 + 1] = fminf(fmaxf(r, 50.0f), 500.0f);
        }
    }
}

extern "C" void kernel_launch(void* const* d_in, const int* in_sizes, int n_in,
                              void* d_out, int out_size)
{
    const float* x = (const float*)d_in[0];
    float* out = (float*)d_out;
    const int pairs = (N_FRAMES + 1) / 2;                       // 321
    dim3 grid((pairs + PAIRS_PER_BLOCK - 1) / PAIRS_PER_BLOCK,  // 41
              64);
    f0_autocorr2_kernel<<<grid, 256>>>(x, out);
}